// round 6
// baseline (speedup 1.0000x reference)
#include <cuda_runtime.h>
#include <math.h>
#include <stdint.h>

#define Bsz 2
#define T 2048
#define Cdim 2048
#define H 16
#define D 128
#define BH (Bsz * H)
#define EPSV 1.1920929e-07f

// ---------------- scratch (static device allocations only) ----------------
__device__ __align__(128) float g_qkv[(size_t)Bsz * T * 3 * Cdim];   // 100 MB
__device__ __align__(128) float g_q[(size_t)BH * T * D];             // 32 MB
__device__ __align__(128) float g_k[(size_t)BH * T * D];             // 32 MB
__device__ __align__(128) float g_v[(size_t)BH * T * D];             // 32 MB
__device__ __align__(128) float g_s[(size_t)BH * T * T];             // 512 MB
__device__ __align__(128) float g_y[(size_t)Bsz * T * Cdim];         // 32 MB
__device__ __align__(128) float g_cos[T * 64];
__device__ __align__(128) float g_sin[T * 64];

// ---------------- helpers ----------------
__device__ __forceinline__ uint32_t f2tf(float f) {
    uint32_t u;
    asm("cvt.rna.tf32.f32 %0, %1;" : "=r"(u) : "f"(f));
    return u;
}

__device__ __forceinline__ void mma_tf32(float* d, const uint32_t* a,
                                         uint32_t b0, uint32_t b1) {
    asm volatile(
        "mma.sync.aligned.m16n8k8.row.col.f32.tf32.tf32.f32 "
        "{%0,%1,%2,%3}, {%4,%5,%6,%7}, {%8,%9}, {%0,%1,%2,%3};\n"
        : "+f"(d[0]), "+f"(d[1]), "+f"(d[2]), "+f"(d[3])
        : "r"(a[0]), "r"(a[1]), "r"(a[2]), "r"(a[3]), "r"(b0), "r"(b1));
}

// ---------------- RoPE tables ----------------
__global__ void rope_tables_kernel() {
    int t = blockIdx.x;
    int j = threadIdx.x;  // 0..63
    double inv = exp(-((double)j / 64.0) * 13.815510557964274);  // ln(1e6)
    double a = (double)t * inv;
    g_cos[t * 64 + j] = (float)cos(a);
    g_sin[t * 64 + j] = (float)sin(a);
}

// ---------------- TF32 MMA tile core (single buffer, R3 structure) ----------------
// Block tile 128x128, BK=16, 256 threads = 8 warps of 32x64 warp-tiles.
// Smem layout per 8-k sub-slab: idx = m*10 + (k&3)*2 + (k>>2); each MMA
// fragment = one aligned LDS.64, (k,k+4) adjacent -> uint2 STS.
// Non-BT B staging: thread covers cols n=(tid&15)+16j -> store banks 10*l
// (all 16 distinct) => conflict-free STS.
template <bool BT>
__device__ __forceinline__ void mma_tile(
    const float* __restrict__ A, int lda,
    const float* __restrict__ B, int ldb,
    float* __restrict__ C, int ldc,
    int K, int row0, int col0)
{
    __shared__ uint32_t As[2560];
    __shared__ uint32_t Bs[2560];

    const int tid  = threadIdx.x;
    const int warp = tid >> 5;
    const int lane = tid & 31;
    const int g = lane >> 2;       // 0..7
    const int c = lane & 3;        // 0..3
    const int wm = (warp >> 1) * 32;
    const int wn = (warp & 1) * 64;

    // A gmem: row = tid>>1 (0..127), k offset = (tid&1)*8
    const int a_row = tid >> 1;
    const float* Ap = A + (size_t)(row0 + a_row) * lda + ((tid & 1) << 3);
    uint32_t* As_st = As + (tid & 1) * 1280 + a_row * 10;

    // B gmem + smem store mapping
    const float* Bp;
    uint32_t* Bs_st;
    if (BT) {
        Bp = B + (size_t)(col0 + (tid >> 1)) * ldb + ((tid & 1) << 3);
        Bs_st = Bs + (tid & 1) * 1280 + (tid >> 1) * 10;
    } else {
        const int kr = tid >> 4;            // 0..15
        const int l  = tid & 15;            // 0..15
        Bp = B + (size_t)kr * ldb + col0 + l;
        const int kk = kr & 7;
        Bs_st = Bs + (kr >> 3) * 1280 + l * 10 + ((kk & 3) << 1) + (kk >> 2);
    }

    float acc[2][8][4];
#pragma unroll
    for (int i = 0; i < 2; i++)
#pragma unroll
        for (int j = 0; j < 8; j++)
#pragma unroll
            for (int r = 0; r < 4; r++) acc[i][j][r] = 0.f;

    // hoisted fragment addresses
    const uint32_t* As_f0 = As + (wm + g) * 10 + c * 2;
    const uint32_t* As_f1 = As + (wm + 8 + g) * 10 + c * 2;
    const uint32_t* As_f2 = As + (wm + 16 + g) * 10 + c * 2;
    const uint32_t* As_f3 = As + (wm + 24 + g) * 10 + c * 2;
    const uint32_t* Bs_f  = Bs + (wn + g) * 10 + c * 2;

    for (int k0 = 0; k0 < K; k0 += 16) {
        // gmem loads (issued before sync -> overlap prior MMA stage)
        float4 av0 = *(const float4*)(Ap + k0);
        float4 av1 = *(const float4*)(Ap + k0 + 4);
        float br[8];
        if (BT) {
            float4 w0 = *(const float4*)(Bp + k0);
            float4 w1 = *(const float4*)(Bp + k0 + 4);
            br[0] = w0.x; br[1] = w0.y; br[2] = w0.z; br[3] = w0.w;
            br[4] = w1.x; br[5] = w1.y; br[6] = w1.z; br[7] = w1.w;
        } else {
            const float* p = Bp + (size_t)k0 * ldb;
#pragma unroll
            for (int t2 = 0; t2 < 8; t2++) br[t2] = p[t2 * 16];
        }
        __syncthreads();
        {
            float av[8] = {av0.x, av0.y, av0.z, av0.w, av1.x, av1.y, av1.z, av1.w};
#pragma unroll
            for (int t2 = 0; t2 < 4; t2++)
                *(uint2*)(As_st + 2 * t2) = make_uint2(f2tf(av[t2]), f2tf(av[t2 + 4]));
            if (BT) {
#pragma unroll
                for (int t2 = 0; t2 < 4; t2++)
                    *(uint2*)(Bs_st + 2 * t2) = make_uint2(f2tf(br[t2]), f2tf(br[t2 + 4]));
            } else {
#pragma unroll
                for (int t2 = 0; t2 < 8; t2++)
                    Bs_st[t2 * 160] = f2tf(br[t2]);   // n += 16 -> +160 words
            }
        }
        __syncthreads();

#pragma unroll
        for (int ks = 0; ks < 2; ks++) {
            const int so = ks * 1280;
            uint32_t a[2][4];
            {
                uint2 lo = *(const uint2*)(As_f0 + so);
                uint2 hi = *(const uint2*)(As_f1 + so);
                a[0][0] = lo.x; a[0][1] = hi.x; a[0][2] = lo.y; a[0][3] = hi.y;
                uint2 lo2 = *(const uint2*)(As_f2 + so);
                uint2 hi2 = *(const uint2*)(As_f3 + so);
                a[1][0] = lo2.x; a[1][1] = hi2.x; a[1][2] = lo2.y; a[1][3] = hi2.y;
            }
#pragma unroll
            for (int j = 0; j < 8; j++) {
                uint2 bb = *(const uint2*)(Bs_f + so + j * 80);
                mma_tf32(acc[0][j], a[0], bb.x, bb.y);
                mma_tf32(acc[1][j], a[1], bb.x, bb.y);
            }
        }
    }

    // epilogue
#pragma unroll
    for (int i = 0; i < 2; i++) {
        int r0 = row0 + wm + i * 16 + g;
#pragma unroll
        for (int j = 0; j < 8; j++) {
            int col = col0 + wn + j * 8 + c * 2;
            *(float2*)&C[(size_t)r0 * ldc + col] = make_float2(acc[i][j][0], acc[i][j][1]);
            *(float2*)&C[(size_t)(r0 + 8) * ldc + col] = make_float2(acc[i][j][2], acc[i][j][3]);
        }
    }
}

// ---------------- GEMM wrappers ----------------
__global__ __launch_bounds__(256, 2)
void gemm_tf32_kernel(const float* __restrict__ A, const float* __restrict__ B,
                      float* __restrict__ C, int K, int lda, int ldb, int ldc)
{
    mma_tile<false>(A, lda, B, ldb, C, ldc, K, blockIdx.y * 128, blockIdx.x * 128);
}

__global__ __launch_bounds__(256, 2)
void attn_s_kernel()
{
    const int kt = blockIdx.x;
    const int qt = blockIdx.y;
    if (kt > qt) return;
    const int bh = blockIdx.z;
    mma_tile<true>(g_q + (size_t)bh * T * D, D,
                   g_k + (size_t)bh * T * D, D,
                   g_s + (size_t)bh * T * T, T,
                   D, qt * 128, kt * 128);
}

__global__ __launch_bounds__(256, 2)
void attn_y_kernel()
{
    const int qt = blockIdx.y;
    const int bh = blockIdx.z;
    const int b = bh >> 4;
    const int h = bh & 15;
    mma_tile<false>(g_s + (size_t)bh * T * T, T,
                    g_v + (size_t)bh * T * D, D,
                    g_y + (size_t)b * T * Cdim + h * D, Cdim,
                    (qt + 1) * 128, qt * 128, 0);
}

// ---------------- RMSNorm + RoPE + scatter ----------------
__global__ __launch_bounds__(128)
void qkv_post_kernel(const float* __restrict__ qw, const float* __restrict__ kw)
{
    const int bt = blockIdx.x;
    const int h  = blockIdx.y;
    const int d  = threadIdx.x;
    const int t  = bt & (T - 1);
    const int b  = bt >> 11;
    const float* base = g_qkv + (size_t)bt * (3 * Cdim);
    float qv = base[h * D + d];
    float kv = base[Cdim + h * D + d];
    float vv = base[2 * Cdim + h * D + d];

    float q2 = qv * qv, k2 = kv * kv;
#pragma unroll
    for (int off = 16; off; off >>= 1) {
        q2 += __shfl_xor_sync(0xffffffffu, q2, off);
        k2 += __shfl_xor_sync(0xffffffffu, k2, off);
    }
    __shared__ float rq[4], rk[4];
    if ((d & 31) == 0) { rq[d >> 5] = q2; rk[d >> 5] = k2; }
    __syncthreads();
    float qms = (rq[0] + rq[1] + rq[2] + rq[3]) * (1.f / D);
    float kms = (rk[0] + rk[1] + rk[2] + rk[3]) * (1.f / D);
    float qn = qv * rsqrtf(qms + EPSV) * qw[d];
    float kn = kv * rsqrtf(kms + EPSV) * kw[d];

    __shared__ float sq[128], sk[128];
    sq[d] = qn; sk[d] = kn;
    __syncthreads();
    int j = d & 63;
    float cc = g_cos[t * 64 + j];
    float ss = g_sin[t * 64 + j];
    float qo, ko;
    if (d < 64) { qo = qn * cc - sq[d + 64] * ss; ko = kn * cc - sk[d + 64] * ss; }
    else        { qo = qn * cc + sq[d - 64] * ss; ko = kn * cc + sk[d - 64] * ss; }

    const size_t o = (((size_t)(b * H + h)) * T + t) * D + d;
    g_q[o] = qo; g_k[o] = ko; g_v[o] = vv;
}

// ---------------- causal softmax (bounded, in place, scale 1/D) ----------------
__global__ __launch_bounds__(256)
void softmax_kernel()
{
    const int row = blockIdx.x;          // bh*T + q
    const int q = row & (T - 1);
    float* Srow = g_s + (size_t)row * T;
    const int tid = threadIdx.x;
    const float scale = 1.0f / (float)D;
    const int nt = (q >> 8) + 1;         // 256-wide chunks needed

    float v[8];
    float m = -3.4e38f;
#pragma unroll
    for (int i = 0; i < 8; i++) {
        if (i >= nt) break;
        int j = (i << 8) + tid;
        float s = (j <= q) ? Srow[j] * scale : -INFINITY;
        v[i] = s;
        m = fmaxf(m, s);
    }
#pragma unroll
    for (int off = 16; off; off >>= 1)
        m = fmaxf(m, __shfl_xor_sync(0xffffffffu, m, off));
    __shared__ float redm[8], reds[8];
    if ((tid & 31) == 0) redm[tid >> 5] = m;
    __syncthreads();
    float bm = redm[0];
#pragma unroll
    for (int w = 1; w < 8; w++) bm = fmaxf(bm, redm[w]);

    float sum = 0.f;
#pragma unroll
    for (int i = 0; i < 8; i++) {
        if (i >= nt) break;
        float p = expf(v[i] - bm);
        v[i] = p;
        sum += p;
    }
#pragma unroll
    for (int off = 16; off; off >>= 1)
        sum += __shfl_xor_sync(0xffffffffu, sum, off);
    if ((tid & 31) == 0) reds[tid >> 5] = sum;
    __syncthreads();
    float bs = reds[0];
#pragma unroll
    for (int w = 1; w < 8; w++) bs += reds[w];
    float inv = 1.0f / bs;
#pragma unroll
    for (int i = 0; i < 8; i++) {
        if (i >= nt) break;
        Srow[(i << 8) + tid] = v[i] * inv;
    }
}

// ---------------- launcher ----------------
extern "C" void kernel_launch(void* const* d_in, const int* in_sizes, int n_in,
                              void* d_out, int out_size)
{
    const float* x      = (const float*)d_in[0];
    const float* w_qkv  = (const float*)d_in[1];
    const float* w_proj = (const float*)d_in[2];
    const float* qw     = (const float*)d_in[3];
    const float* kw     = (const float*)d_in[4];
    float* out = (float*)d_out;

    float *p_qkv = nullptr, *p_y = nullptr;
    cudaGetSymbolAddress((void**)&p_qkv, g_qkv);
    cudaGetSymbolAddress((void**)&p_y, g_y);

    // 1. RoPE tables
    rope_tables_kernel<<<T, 64>>>();
    // 2. qkv = x @ w_qkv   (M=4096, N=6144, K=2048)
    gemm_tf32_kernel<<<dim3(3 * Cdim / 128, (Bsz * T) / 128), 256>>>(
        x, w_qkv, p_qkv, Cdim, Cdim, 3 * Cdim, 3 * Cdim);
    // 3. RMSNorm + RoPE + scatter into [BH,T,D]
    qkv_post_kernel<<<dim3(Bsz * T, H), 128>>>(qw, kw);
    // 4. S = Q @ K^T (causal tile skip)
    attn_s_kernel<<<dim3(T / 128, T / 128, BH), 256>>>();
    // 5. causal softmax (scale 1/D), in-place S -> P
    softmax_kernel<<<BH * T, 256>>>();
    // 6. Y = P @ V written to [B,T,C]
    attn_y_kernel<<<dim3(1, T / 128, BH), 256>>>();
    // 7. out = y @ w_proj  (M=4096, N=2048, K=2048)
    gemm_tf32_kernel<<<dim3(Cdim / 128, (Bsz * T) / 128), 256>>>(
        p_y, w_proj, out, Cdim, Cdim, Cdim, Cdim);
}

// round 8
// speedup vs baseline: 1.2709x; 1.2709x over previous
#include <cuda_runtime.h>
#include <math.h>
#include <stdint.h>

#define Bsz 2
#define T 2048
#define Cdim 2048
#define H 16
#define D 128
#define BH (Bsz * H)
#define EPSV 1.1920929e-07f

// ---------------- scratch (static device allocations only) ----------------
__device__ __align__(128) float g_qkv[(size_t)Bsz * T * 3 * Cdim];   // 100 MB
__device__ __align__(128) float g_q[(size_t)BH * T * D];             // 32 MB
__device__ __align__(128) float g_k[(size_t)BH * T * D];             // 32 MB
__device__ __align__(128) float g_v[(size_t)BH * T * D];             // 32 MB
__device__ __align__(128) float g_s[(size_t)BH * T * T];             // 512 MB
__device__ __align__(128) float g_y[(size_t)Bsz * T * Cdim];         // 32 MB
__device__ __align__(128) float g_cos[T * 64];
__device__ __align__(128) float g_sin[T * 64];

// ---------------- helpers ----------------
__device__ __forceinline__ uint32_t f2tf(float f) {
    uint32_t u;
    asm("cvt.rna.tf32.f32 %0, %1;" : "=r"(u) : "f"(f));
    return u;
}

__device__ __forceinline__ void mma_tf32(float* d, const uint32_t* a,
                                         uint32_t b0, uint32_t b1) {
    asm volatile(
        "mma.sync.aligned.m16n8k8.row.col.f32.tf32.tf32.f32 "
        "{%0,%1,%2,%3}, {%4,%5,%6,%7}, {%8,%9}, {%0,%1,%2,%3};\n"
        : "+f"(d[0]), "+f"(d[1]), "+f"(d[2]), "+f"(d[3])
        : "r"(a[0]), "r"(a[1]), "r"(a[2]), "r"(a[3]), "r"(b0), "r"(b1));
}

// ---------------- RoPE tables ----------------
__global__ void rope_tables_kernel() {
    int t = blockIdx.x;
    int j = threadIdx.x;  // 0..63
    double inv = exp(-((double)j / 64.0) * 13.815510557964274);  // ln(1e6)
    double a = (double)t * inv;
    g_cos[t * 64 + j] = (float)cos(a);
    g_sin[t * 64 + j] = (float)sin(a);
}

// ---------------- TF32 MMA tile core (exact R3 version, measured 2699us) ----------------
// Block tile 128x128, BK=16, 256 threads = 8 warps of 32x64 warp-tiles.
// Smem layout (per k-step slab of 8 ks): idx = m*10 + (k&3)*2 + (k>>2), so
// each fragment is one aligned LDS.64. Slab stride = 1280 u32.
// BT=false: B is [K,N] row-major (ldb = row stride).
// BT=true : B is [N,K] row-major (ldb = row stride) -> computes A @ B^T.
template <bool BT>
__device__ __forceinline__ void mma_tile(
    const float* __restrict__ A, int lda,
    const float* __restrict__ B, int ldb,
    float* __restrict__ C, int ldc,
    int K, int row0, int col0)
{
    __shared__ uint32_t As[2 * 1280];
    __shared__ uint32_t Bs[2 * 1280];

    const int tid  = threadIdx.x;
    const int warp = tid >> 5;
    const int lane = tid & 31;
    const int g = lane >> 2;       // 0..7
    const int c = lane & 3;        // 0..3
    const int wm = (warp >> 1) * 32;
    const int wn = (warp & 1) * 64;

    // A gmem mapping: row = tid>>1 (0..127), k offset = (tid&1)*8
    const int a_row = tid >> 1;
    const int a_kc  = (tid & 1) << 3;
    const float* Ap = A + (size_t)(row0 + a_row) * lda + a_kc;
    // A smem store base: slab = (tid&1)
    uint32_t* As_st = As + (tid & 1) * 1280 + a_row * 10;

    // B gmem mapping
    const float* Bp;
    uint32_t* Bs_st;
    int b_coff = 0;
    if (BT) {
        // read rows of B[N,K]: n = tid>>1, k offset = (tid&1)*8
        const int n  = tid >> 1;
        const int kc = (tid & 1) << 3;
        Bp = B + (size_t)(col0 + n) * ldb + kc;
        Bs_st = Bs + (tid & 1) * 1280 + n * 10;
    } else {
        // read rows of B[K,N]: k = tid>>4 (0..15), n offset = (tid&15)*8
        const int kr = tid >> 4;
        const int nc = (tid & 15) << 3;
        Bp = B + (size_t)kr * ldb + col0 + nc;
        const int kk = kr & 7;
        b_coff = ((kk & 3) << 1) + (kk >> 2);
        Bs_st = Bs + (kr >> 3) * 1280 + nc * 10;
    }

    float acc[2][8][4];
#pragma unroll
    for (int i = 0; i < 2; i++)
#pragma unroll
        for (int j = 0; j < 8; j++)
#pragma unroll
            for (int r = 0; r < 4; r++) acc[i][j][r] = 0.f;

    // interleave permutation for 8 consecutive k values
    const int kperm[8] = {0, 2, 4, 6, 1, 3, 5, 7};

    for (int k0 = 0; k0 < K; k0 += 16) {
        // stage gmem
        float4 av0 = *(const float4*)(Ap + k0);
        float4 av1 = *(const float4*)(Ap + k0 + 4);
        float4 bv0, bv1;
        if (BT) {
            bv0 = *(const float4*)(Bp + k0);
            bv1 = *(const float4*)(Bp + k0 + 4);
        } else {
            bv0 = *(const float4*)(Bp + (size_t)k0 * ldb);
            bv1 = *(const float4*)(Bp + (size_t)k0 * ldb + 4);
        }
        __syncthreads();
        {
            float av[8] = {av0.x, av0.y, av0.z, av0.w, av1.x, av1.y, av1.z, av1.w};
#pragma unroll
            for (int t2 = 0; t2 < 8; t2++) As_st[kperm[t2]] = f2tf(av[t2]);
            float bvv[8] = {bv0.x, bv0.y, bv0.z, bv0.w, bv1.x, bv1.y, bv1.z, bv1.w};
            if (BT) {
#pragma unroll
                for (int t2 = 0; t2 < 8; t2++) Bs_st[kperm[t2]] = f2tf(bvv[t2]);
            } else {
#pragma unroll
                for (int t2 = 0; t2 < 8; t2++) Bs_st[t2 * 10 + b_coff] = f2tf(bvv[t2]);
            }
        }
        __syncthreads();

#pragma unroll
        for (int ks = 0; ks < 2; ks++) {
            const uint32_t* as = As + ks * 1280;
            const uint32_t* bs = Bs + ks * 1280;
            uint32_t a[2][4];
#pragma unroll
            for (int i = 0; i < 2; i++) {
                int r = wm + i * 16 + g;
                uint2 lo = *(const uint2*)&as[r * 10 + c * 2];
                uint2 hi = *(const uint2*)&as[(r + 8) * 10 + c * 2];
                a[i][0] = lo.x; a[i][1] = hi.x; a[i][2] = lo.y; a[i][3] = hi.y;
            }
#pragma unroll
            for (int j = 0; j < 8; j++) {
                int n = wn + j * 8 + g;
                uint2 bb = *(const uint2*)&bs[n * 10 + c * 2];
#pragma unroll
                for (int i = 0; i < 2; i++)
                    mma_tf32(acc[i][j], a[i], bb.x, bb.y);
            }
        }
    }

    // epilogue: c0,c1 -> (row g, cols 2c,2c+1); c2,c3 -> (row g+8)
#pragma unroll
    for (int i = 0; i < 2; i++) {
        int r0 = row0 + wm + i * 16 + g;
#pragma unroll
        for (int j = 0; j < 8; j++) {
            int col = col0 + wn + j * 8 + c * 2;
            *(float2*)&C[(size_t)r0 * ldc + col] = make_float2(acc[i][j][0], acc[i][j][1]);
            *(float2*)&C[(size_t)(r0 + 8) * ldc + col] = make_float2(acc[i][j][2], acc[i][j][3]);
        }
    }
}

// ---------------- GEMM wrappers ----------------
__global__ __launch_bounds__(256, 2)
void gemm_tf32_kernel(const float* __restrict__ A, const float* __restrict__ B,
                      float* __restrict__ C, int K, int lda, int ldb, int ldc)
{
    mma_tile<false>(A, lda, B, ldb, C, ldc, K, blockIdx.y * 128, blockIdx.x * 128);
}

__global__ __launch_bounds__(256, 2)
void attn_s_kernel()
{
    const int kt = blockIdx.x;
    const int qt = blockIdx.y;
    if (kt > qt) return;
    const int bh = blockIdx.z;
    mma_tile<true>(g_q + (size_t)bh * T * D, D,
                   g_k + (size_t)bh * T * D, D,
                   g_s + (size_t)bh * T * T, T,
                   D, qt * 128, kt * 128);
}

__global__ __launch_bounds__(256, 2)
void attn_y_kernel()
{
    const int qt = blockIdx.y;
    const int bh = blockIdx.z;
    const int b = bh >> 4;
    const int h = bh & 15;
    mma_tile<false>(g_s + (size_t)bh * T * T, T,
                    g_v + (size_t)bh * T * D, D,
                    g_y + (size_t)b * T * Cdim + h * D, Cdim,
                    (qt + 1) * 128, qt * 128, 0);
}

// ---------------- RMSNorm + RoPE + scatter ----------------
__global__ __launch_bounds__(128)
void qkv_post_kernel(const float* __restrict__ qw, const float* __restrict__ kw)
{
    const int bt = blockIdx.x;
    const int h  = blockIdx.y;
    const int d  = threadIdx.x;
    const int t  = bt & (T - 1);
    const int b  = bt >> 11;
    const float* base = g_qkv + (size_t)bt * (3 * Cdim);
    float qv = base[h * D + d];
    float kv = base[Cdim + h * D + d];
    float vv = base[2 * Cdim + h * D + d];

    float q2 = qv * qv, k2 = kv * kv;
#pragma unroll
    for (int off = 16; off; off >>= 1) {
        q2 += __shfl_xor_sync(0xffffffffu, q2, off);
        k2 += __shfl_xor_sync(0xffffffffu, k2, off);
    }
    __shared__ float rq[4], rk[4];
    if ((d & 31) == 0) { rq[d >> 5] = q2; rk[d >> 5] = k2; }
    __syncthreads();
    float qms = (rq[0] + rq[1] + rq[2] + rq[3]) * (1.f / D);
    float kms = (rk[0] + rk[1] + rk[2] + rk[3]) * (1.f / D);
    float qn = qv * rsqrtf(qms + EPSV) * qw[d];
    float kn = kv * rsqrtf(kms + EPSV) * kw[d];

    __shared__ float sq[128], sk[128];
    sq[d] = qn; sk[d] = kn;
    __syncthreads();
    int j = d & 63;
    float cc = g_cos[t * 64 + j];
    float ss = g_sin[t * 64 + j];
    float qo, ko;
    if (d < 64) { qo = qn * cc - sq[d + 64] * ss; ko = kn * cc - sk[d + 64] * ss; }
    else        { qo = qn * cc + sq[d - 64] * ss; ko = kn * cc + sk[d - 64] * ss; }

    const size_t o = (((size_t)(b * H + h)) * T + t) * D + d;
    g_q[o] = qo; g_k[o] = ko; g_v[o] = vv;
}

// ---------------- causal softmax (bounded, in place, scale 1/D) ----------------
__global__ __launch_bounds__(256)
void softmax_kernel()
{
    const int row = blockIdx.x;          // bh*T + q
    const int q = row & (T - 1);
    float* Srow = g_s + (size_t)row * T;
    const int tid = threadIdx.x;
    const float scale = 1.0f / (float)D;
    const int nt = (q >> 8) + 1;         // 256-wide chunks needed

    float v[8];
    float m = -3.4e38f;
#pragma unroll
    for (int i = 0; i < 8; i++) {
        if (i >= nt) break;
        int j = (i << 8) + tid;
        float s = (j <= q) ? Srow[j] * scale : -INFINITY;
        v[i] = s;
        m = fmaxf(m, s);
    }
#pragma unroll
    for (int off = 16; off; off >>= 1)
        m = fmaxf(m, __shfl_xor_sync(0xffffffffu, m, off));
    __shared__ float redm[8], reds[8];
    if ((tid & 31) == 0) redm[tid >> 5] = m;
    __syncthreads();
    float bm = redm[0];
#pragma unroll
    for (int w = 1; w < 8; w++) bm = fmaxf(bm, redm[w]);

    float sum = 0.f;
#pragma unroll
    for (int i = 0; i < 8; i++) {
        if (i >= nt) break;
        float p = expf(v[i] - bm);
        v[i] = p;
        sum += p;
    }
#pragma unroll
    for (int off = 16; off; off >>= 1)
        sum += __shfl_xor_sync(0xffffffffu, sum, off);
    if ((tid & 31) == 0) reds[tid >> 5] = sum;
    __syncthreads();
    float bs = reds[0];
#pragma unroll
    for (int w = 1; w < 8; w++) bs += reds[w];
    float inv = 1.0f / bs;
#pragma unroll
    for (int i = 0; i < 8; i++) {
        if (i >= nt) break;
        Srow[(i << 8) + tid] = v[i] * inv;
    }
}

// ---------------- launcher ----------------
extern "C" void kernel_launch(void* const* d_in, const int* in_sizes, int n_in,
                              void* d_out, int out_size)
{
    const float* x      = (const float*)d_in[0];
    const float* w_qkv  = (const float*)d_in[1];
    const float* w_proj = (const float*)d_in[2];
    const float* qw     = (const float*)d_in[3];
    const float* kw     = (const float*)d_in[4];
    float* out = (float*)d_out;

    float *p_qkv = nullptr, *p_y = nullptr;
    cudaGetSymbolAddress((void**)&p_qkv, g_qkv);
    cudaGetSymbolAddress((void**)&p_y, g_y);

    // 1. RoPE tables
    rope_tables_kernel<<<T, 64>>>();
    // 2. qkv = x @ w_qkv   (M=4096, N=6144, K=2048)
    gemm_tf32_kernel<<<dim3(3 * Cdim / 128, (Bsz * T) / 128), 256>>>(
        x, w_qkv, p_qkv, Cdim, Cdim, 3 * Cdim, 3 * Cdim);
    // 3. RMSNorm + RoPE + scatter into [BH,T,D]
    qkv_post_kernel<<<dim3(Bsz * T, H), 128>>>(qw, kw);
    // 4. S = Q @ K^T (causal tile skip)
    attn_s_kernel<<<dim3(T / 128, T / 128, BH), 256>>>();
    // 5. causal softmax (scale 1/D), in-place S -> P
    softmax_kernel<<<BH * T, 256>>>();
    // 6. Y = P @ V written to [B,T,C]
    attn_y_kernel<<<dim3(1, T / 128, BH), 256>>>();
    // 7. out = y @ w_proj  (M=4096, N=2048, K=2048)
    gemm_tf32_kernel<<<dim3(Cdim / 128, (Bsz * T) / 128), 256>>>(
        p_y, w_proj, out, Cdim, Cdim, Cdim, Cdim);
}

// round 11
// speedup vs baseline: 1.3517x; 1.0636x over previous
#include <cuda_runtime.h>
#include <math.h>
#include <stdint.h>

#define Bsz 2
#define T 2048
#define Cdim 2048
#define H 16
#define D 128
#define BH (Bsz * H)
#define EPSV 1.1920929e-07f

// ---------------- scratch (static device allocations only) ----------------
__device__ __align__(128) float g_qkv[(size_t)Bsz * T * 3 * Cdim];   // 100 MB
__device__ __align__(128) float g_q[(size_t)BH * T * D];             // 32 MB
__device__ __align__(128) float g_k[(size_t)BH * T * D];             // 32 MB
__device__ __align__(128) float g_v[(size_t)BH * T * D];             // 32 MB
__device__ __align__(128) float g_y[(size_t)Bsz * T * Cdim];         // 32 MB
__device__ __align__(128) float g_cos[T * 64];
__device__ __align__(128) float g_sin[T * 64];

// ---------------- helpers ----------------
__device__ __forceinline__ uint32_t f2tf(float f) {
    uint32_t u;
    asm("cvt.rna.tf32.f32 %0, %1;" : "=r"(u) : "f"(f));
    return u;
}

__device__ __forceinline__ void mma_tf32(float* d, const uint32_t* a,
                                         uint32_t b0, uint32_t b1) {
    asm volatile(
        "mma.sync.aligned.m16n8k8.row.col.f32.tf32.tf32.f32 "
        "{%0,%1,%2,%3}, {%4,%5,%6,%7}, {%8,%9}, {%0,%1,%2,%3};\n"
        : "+f"(d[0]), "+f"(d[1]), "+f"(d[2]), "+f"(d[3])
        : "r"(a[0]), "r"(a[1]), "r"(a[2]), "r"(a[3]), "r"(b0), "r"(b1));
}

// ---------------- RoPE tables ----------------
__global__ void rope_tables_kernel() {
    int t = blockIdx.x;
    int j = threadIdx.x;  // 0..63
    double inv = exp(-((double)j / 64.0) * 13.815510557964274);  // ln(1e6)
    double a = (double)t * inv;
    g_cos[t * 64 + j] = (float)cos(a);
    g_sin[t * 64 + j] = (float)sin(a);
}

// ---------------- TF32 MMA tile core (exact R3 version, measured 2696us) ----------------
template <bool BT>
__device__ __forceinline__ void mma_tile(
    const float* __restrict__ A, int lda,
    const float* __restrict__ B, int ldb,
    float* __restrict__ C, int ldc,
    int K, int row0, int col0)
{
    __shared__ uint32_t As[2 * 1280];
    __shared__ uint32_t Bs[2 * 1280];

    const int tid  = threadIdx.x;
    const int warp = tid >> 5;
    const int lane = tid & 31;
    const int g = lane >> 2;
    const int c = lane & 3;
    const int wm = (warp >> 1) * 32;
    const int wn = (warp & 1) * 64;

    const int a_row = tid >> 1;
    const int a_kc  = (tid & 1) << 3;
    const float* Ap = A + (size_t)(row0 + a_row) * lda + a_kc;
    uint32_t* As_st = As + (tid & 1) * 1280 + a_row * 10;

    const float* Bp;
    uint32_t* Bs_st;
    int b_coff = 0;
    if (BT) {
        const int n  = tid >> 1;
        const int kc = (tid & 1) << 3;
        Bp = B + (size_t)(col0 + n) * ldb + kc;
        Bs_st = Bs + (tid & 1) * 1280 + n * 10;
    } else {
        const int kr = tid >> 4;
        const int nc = (tid & 15) << 3;
        Bp = B + (size_t)kr * ldb + col0 + nc;
        const int kk = kr & 7;
        b_coff = ((kk & 3) << 1) + (kk >> 2);
        Bs_st = Bs + (kr >> 3) * 1280 + nc * 10;
    }

    float acc[2][8][4];
#pragma unroll
    for (int i = 0; i < 2; i++)
#pragma unroll
        for (int j = 0; j < 8; j++)
#pragma unroll
            for (int r = 0; r < 4; r++) acc[i][j][r] = 0.f;

    const int kperm[8] = {0, 2, 4, 6, 1, 3, 5, 7};

    for (int k0 = 0; k0 < K; k0 += 16) {
        float4 av0 = *(const float4*)(Ap + k0);
        float4 av1 = *(const float4*)(Ap + k0 + 4);
        float4 bv0, bv1;
        if (BT) {
            bv0 = *(const float4*)(Bp + k0);
            bv1 = *(const float4*)(Bp + k0 + 4);
        } else {
            bv0 = *(const float4*)(Bp + (size_t)k0 * ldb);
            bv1 = *(const float4*)(Bp + (size_t)k0 * ldb + 4);
        }
        __syncthreads();
        {
            float av[8] = {av0.x, av0.y, av0.z, av0.w, av1.x, av1.y, av1.z, av1.w};
#pragma unroll
            for (int t2 = 0; t2 < 8; t2++) As_st[kperm[t2]] = f2tf(av[t2]);
            float bvv[8] = {bv0.x, bv0.y, bv0.z, bv0.w, bv1.x, bv1.y, bv1.z, bv1.w};
            if (BT) {
#pragma unroll
                for (int t2 = 0; t2 < 8; t2++) Bs_st[kperm[t2]] = f2tf(bvv[t2]);
            } else {
#pragma unroll
                for (int t2 = 0; t2 < 8; t2++) Bs_st[t2 * 10 + b_coff] = f2tf(bvv[t2]);
            }
        }
        __syncthreads();

#pragma unroll
        for (int ks = 0; ks < 2; ks++) {
            const uint32_t* as = As + ks * 1280;
            const uint32_t* bs = Bs + ks * 1280;
            uint32_t a[2][4];
#pragma unroll
            for (int i = 0; i < 2; i++) {
                int r = wm + i * 16 + g;
                uint2 lo = *(const uint2*)&as[r * 10 + c * 2];
                uint2 hi = *(const uint2*)&as[(r + 8) * 10 + c * 2];
                a[i][0] = lo.x; a[i][1] = hi.x; a[i][2] = lo.y; a[i][3] = hi.y;
            }
#pragma unroll
            for (int j = 0; j < 8; j++) {
                int n = wn + j * 8 + g;
                uint2 bb = *(const uint2*)&bs[n * 10 + c * 2];
#pragma unroll
                for (int i = 0; i < 2; i++)
                    mma_tf32(acc[i][j], a[i], bb.x, bb.y);
            }
        }
    }

#pragma unroll
    for (int i = 0; i < 2; i++) {
        int r0 = row0 + wm + i * 16 + g;
#pragma unroll
        for (int j = 0; j < 8; j++) {
            int col = col0 + wn + j * 8 + c * 2;
            *(float2*)&C[(size_t)r0 * ldc + col] = make_float2(acc[i][j][0], acc[i][j][1]);
            *(float2*)&C[(size_t)(r0 + 8) * ldc + col] = make_float2(acc[i][j][2], acc[i][j][3]);
        }
    }
}

__global__ __launch_bounds__(256, 2)
void gemm_tf32_kernel(const float* __restrict__ A, const float* __restrict__ B,
                      float* __restrict__ C, int K, int lda, int ldb, int ldc)
{
    mma_tile<false>(A, lda, B, ldb, C, ldc, K, blockIdx.y * 128, blockIdx.x * 128);
}

// ---------------- fused flash attention ----------------
// One block = (bh, 128 q rows). Loops over causal k-tiles:
// S = Q K^T (R3 BT staging) -> online softmax in regs -> P to smem in
// A-fragment layout -> O += P V (R3 non-BT staging for V). O written with 1/l.
// Dynamic smem: As 2560 | Bs 2560 | Ps 20480 | stats 512  (u32) = 104448 B.
#define FA_SMEM_BYTES (26112 * 4)

__global__ __launch_bounds__(256, 1)
void flash_attn_kernel()
{
    extern __shared__ uint32_t sm[];
    uint32_t* As = sm;
    uint32_t* Bs = sm + 2560;
    uint32_t* Ps = sm + 5120;
    float* sm_m = (float*)(sm + 25600);   // [2][128]
    float* sm_l = sm_m + 256;             // [2][128]

    const int bh = blockIdx.x;
    const int qt = (int)gridDim.y - 1 - (int)blockIdx.y;   // heavy tiles first
    const float* Q  = g_q + (size_t)bh * T * D;
    const float* Km = g_k + (size_t)bh * T * D;
    const float* V  = g_v + (size_t)bh * T * D;

    const int tid  = threadIdx.x;
    const int warp = tid >> 5;
    const int lane = tid & 31;
    const int g = lane >> 2;
    const int c = lane & 3;
    const int wm = (warp >> 1) * 32;
    const int wn = (warp & 1) * 64;
    const int half = warp & 1;

    // Q staging (A role)
    const int a_row = tid >> 1;
    const float* Qp = Q + (size_t)(qt * 128 + a_row) * D + ((tid & 1) << 3);
    uint32_t* As_st = As + (tid & 1) * 1280 + a_row * 10;
    // K staging (BT role)
    uint32_t* Bs_stK = Bs + (tid & 1) * 1280 + (tid >> 1) * 10;
    // V staging (non-BT role)
    const int kr = tid >> 4;
    const int nc = (tid & 15) << 3;
    const int kk7 = kr & 7;
    const int v_coff = ((kk7 & 3) << 1) + (kk7 >> 2);
    uint32_t* Bs_stV = Bs + (kr >> 3) * 1280 + nc * 10;

    const int kperm[8] = {0, 2, 4, 6, 1, 3, 5, 7};
    const int slot0 = ((c & 1) << 2) | (c >> 1);   // P-store slot for k=2c

    float oacc[2][8][4];
#pragma unroll
    for (int i = 0; i < 2; i++)
#pragma unroll
        for (int j = 0; j < 8; j++)
#pragma unroll
            for (int r = 0; r < 4; r++) oacc[i][j][r] = 0.f;

    float mrow[4], lsum[4];
    int lr[4];
#pragma unroll
    for (int q = 0; q < 4; q++) {
        mrow[q] = -1e30f; lsum[q] = 0.f;
        lr[q] = wm + 16 * (q >> 1) + 8 * (q & 1) + g;
    }
    const float scale = 1.0f / (float)D;

    for (int kt = 0; kt <= qt; kt++) {
        // ======== S = Q @ K^T over this k-tile ========
        float acc[2][8][4];
#pragma unroll
        for (int i = 0; i < 2; i++)
#pragma unroll
            for (int j = 0; j < 8; j++)
#pragma unroll
                for (int r = 0; r < 4; r++) acc[i][j][r] = 0.f;

        const float* Kp = Km + (size_t)(kt * 128 + (tid >> 1)) * D + ((tid & 1) << 3);
        for (int k0 = 0; k0 < 128; k0 += 16) {
            float4 av0 = *(const float4*)(Qp + k0);
            float4 av1 = *(const float4*)(Qp + k0 + 4);
            float4 bv0 = *(const float4*)(Kp + k0);
            float4 bv1 = *(const float4*)(Kp + k0 + 4);
            __syncthreads();
            {
                float av[8] = {av0.x, av0.y, av0.z, av0.w, av1.x, av1.y, av1.z, av1.w};
                float bv[8] = {bv0.x, bv0.y, bv0.z, bv0.w, bv1.x, bv1.y, bv1.z, bv1.w};
#pragma unroll
                for (int t2 = 0; t2 < 8; t2++) As_st[kperm[t2]] = f2tf(av[t2]);
#pragma unroll
                for (int t2 = 0; t2 < 8; t2++) Bs_stK[kperm[t2]] = f2tf(bv[t2]);
            }
            __syncthreads();
#pragma unroll
            for (int ks = 0; ks < 2; ks++) {
                const uint32_t* as = As + ks * 1280;
                const uint32_t* bs = Bs + ks * 1280;
                uint32_t a[2][4];
#pragma unroll
                for (int i = 0; i < 2; i++) {
                    int r = wm + i * 16 + g;
                    uint2 lo = *(const uint2*)&as[r * 10 + c * 2];
                    uint2 hi = *(const uint2*)&as[(r + 8) * 10 + c * 2];
                    a[i][0] = lo.x; a[i][1] = hi.x; a[i][2] = lo.y; a[i][3] = hi.y;
                }
#pragma unroll
                for (int j = 0; j < 8; j++) {
                    int n = wn + j * 8 + g;
                    uint2 bb = *(const uint2*)&bs[n * 10 + c * 2];
#pragma unroll
                    for (int i = 0; i < 2; i++)
                        mma_tf32(acc[i][j], a[i], bb.x, bb.y);
                }
            }
        }

        // ======== online softmax update ========
        const bool diag = (kt == qt);
        // per-row tile max (scale + mask applied in place)
#pragma unroll
        for (int q = 0; q < 4; q++) {
            const int i = q >> 1, rb = (q & 1) * 2;
            float rm = -1e30f;
#pragma unroll
            for (int j = 0; j < 8; j++) {
#pragma unroll
                for (int v = 0; v < 2; v++) {
                    float s = acc[i][j][rb + v] * scale;
                    if (diag && (wn + 8 * j + 2 * c + v > lr[q])) s = -1e30f;
                    acc[i][j][rb + v] = s;
                    rm = fmaxf(rm, s);
                }
            }
            rm = fmaxf(rm, __shfl_xor_sync(0xffffffffu, rm, 1));
            rm = fmaxf(rm, __shfl_xor_sync(0xffffffffu, rm, 2));
            if (c == 0) sm_m[half * 128 + lr[q]] = rm;
        }
        __syncthreads();
        float alpha_s[4];
#pragma unroll
        for (int q = 0; q < 4; q++) {
            const int i = q >> 1, rb = (q & 1) * 2;
            float tm = fmaxf(sm_m[lr[q]], sm_m[128 + lr[q]]);
            float nm = fmaxf(mrow[q], tm);
            float alpha = expf(mrow[q] - nm);
            mrow[q] = nm;
            alpha_s[q] = alpha;
            float rs = 0.f;
#pragma unroll
            for (int j = 0; j < 8; j++) {
#pragma unroll
                for (int v = 0; v < 2; v++) {
                    float p = expf(acc[i][j][rb + v] - nm);
                    acc[i][j][rb + v] = p;
                    rs += p;
                }
            }
            rs += __shfl_xor_sync(0xffffffffu, rs, 1);
            rs += __shfl_xor_sync(0xffffffffu, rs, 2);
            if (c == 0) sm_l[half * 128 + lr[q]] = rs;
            // rescale O accumulators
#pragma unroll
            for (int j = 0; j < 8; j++) {
                oacc[i][j][rb]     *= alpha;
                oacc[i][j][rb + 1] *= alpha;
            }
        }
        __syncthreads();
#pragma unroll
        for (int q = 0; q < 4; q++)
            lsum[q] = lsum[q] * alpha_s[q] + sm_l[lr[q]] + sm_l[128 + lr[q]];

        // ======== store P (tf32) into A-fragment layout ========
#pragma unroll
        for (int q = 0; q < 4; q++) {
            const int i = q >> 1, rb = (q & 1) * 2;
            uint32_t* prow = Ps + lr[q] * 10;
#pragma unroll
            for (int j = 0; j < 8; j++) {
                uint32_t* pp = prow + ((wn >> 3) + j) * 1280;
                pp[slot0]     = f2tf(acc[i][j][rb]);
                pp[slot0 + 2] = f2tf(acc[i][j][rb + 1]);
            }
        }

        // ======== O += P @ V ========
        for (int sl = 0; sl < 8; sl++) {
            const float* vp = V + (size_t)(kt * 128 + sl * 16 + kr) * D + nc;
            float4 w0 = *(const float4*)vp;
            float4 w1 = *(const float4*)(vp + 4);
            __syncthreads();   // also makes P stores visible before first read
            {
                float bvv[8] = {w0.x, w0.y, w0.z, w0.w, w1.x, w1.y, w1.z, w1.w};
#pragma unroll
                for (int t2 = 0; t2 < 8; t2++)
                    Bs_stV[t2 * 10 + v_coff] = f2tf(bvv[t2]);
            }
            __syncthreads();
#pragma unroll
            for (int ks = 0; ks < 2; ks++) {
                const uint32_t* as = Ps + (sl * 2 + ks) * 1280;
                const uint32_t* bs = Bs + ks * 1280;
                uint32_t a[2][4];
#pragma unroll
                for (int i = 0; i < 2; i++) {
                    int r = wm + i * 16 + g;
                    uint2 lo = *(const uint2*)&as[r * 10 + c * 2];
                    uint2 hi = *(const uint2*)&as[(r + 8) * 10 + c * 2];
                    a[i][0] = lo.x; a[i][1] = hi.x; a[i][2] = lo.y; a[i][3] = hi.y;
                }
#pragma unroll
                for (int j = 0; j < 8; j++) {
                    int n = wn + j * 8 + g;
                    uint2 bb = *(const uint2*)&bs[n * 10 + c * 2];
#pragma unroll
                    for (int i = 0; i < 2; i++)
                        mma_tf32(oacc[i][j], a[i], bb.x, bb.y);
                }
            }
        }
    }

    // ======== epilogue: normalize and write to [B,T,C] ========
    const int b = bh >> 4;
    const int h = bh & 15;
    float* Cbase = g_y + (size_t)b * T * Cdim + h * D;
#pragma unroll
    for (int i = 0; i < 2; i++) {
#pragma unroll
        for (int rp = 0; rp < 2; rp++) {
            const int q = i * 2 + rp;
            const int row = qt * 128 + lr[q];
            const float inv = 1.0f / lsum[q];
            const int rb = rp * 2;
#pragma unroll
            for (int j = 0; j < 8; j++) {
                int col = wn + j * 8 + c * 2;
                *(float2*)&Cbase[(size_t)row * Cdim + col] =
                    make_float2(oacc[i][j][rb] * inv, oacc[i][j][rb + 1] * inv);
            }
        }
    }
}

// ---------------- RMSNorm + RoPE + scatter ----------------
__global__ __launch_bounds__(128)
void qkv_post_kernel(const float* __restrict__ qw, const float* __restrict__ kw)
{
    const int bt = blockIdx.x;
    const int h  = blockIdx.y;
    const int d  = threadIdx.x;
    const int t  = bt & (T - 1);
    const int b  = bt >> 11;
    const float* base = g_qkv + (size_t)bt * (3 * Cdim);
    float qv = base[h * D + d];
    float kv = base[Cdim + h * D + d];
    float vv = base[2 * Cdim + h * D + d];

    float q2 = qv * qv, k2 = kv * kv;
#pragma unroll
    for (int off = 16; off; off >>= 1) {
        q2 += __shfl_xor_sync(0xffffffffu, q2, off);
        k2 += __shfl_xor_sync(0xffffffffu, k2, off);
    }
    __shared__ float rq[4], rk[4];
    if ((d & 31) == 0) { rq[d >> 5] = q2; rk[d >> 5] = k2; }
    __syncthreads();
    float qms = (rq[0] + rq[1] + rq[2] + rq[3]) * (1.f / D);
    float kms = (rk[0] + rk[1] + rk[2] + rk[3]) * (1.f / D);
    float qn = qv * rsqrtf(qms + EPSV) * qw[d];
    float kn = kv * rsqrtf(kms + EPSV) * kw[d];

    __shared__ float sq[128], sk[128];
    sq[d] = qn; sk[d] = kn;
    __syncthreads();
    int j = d & 63;
    float cc = g_cos[t * 64 + j];
    float ss = g_sin[t * 64 + j];
    float qo, ko;
    if (d < 64) { qo = qn * cc - sq[d + 64] * ss; ko = kn * cc - sk[d + 64] * ss; }
    else        { qo = qn * cc + sq[d - 64] * ss; ko = kn * cc + sk[d - 64] * ss; }

    const size_t o = (((size_t)(b * H + h)) * T + t) * D + d;
    g_q[o] = qo; g_k[o] = ko; g_v[o] = vv;
}

// ---------------- launcher ----------------
extern "C" void kernel_launch(void* const* d_in, const int* in_sizes, int n_in,
                              void* d_out, int out_size)
{
    const float* x      = (const float*)d_in[0];
    const float* w_qkv  = (const float*)d_in[1];
    const float* w_proj = (const float*)d_in[2];
    const float* qw     = (const float*)d_in[3];
    const float* kw     = (const float*)d_in[4];
    float* out = (float*)d_out;

    float *p_qkv = nullptr, *p_y = nullptr;
    cudaGetSymbolAddress((void**)&p_qkv, g_qkv);
    cudaGetSymbolAddress((void**)&p_y, g_y);

    cudaFuncSetAttribute(flash_attn_kernel,
                         cudaFuncAttributeMaxDynamicSharedMemorySize,
                         FA_SMEM_BYTES);

    // 1. RoPE tables
    rope_tables_kernel<<<T, 64>>>();
    // 2. qkv = x @ w_qkv   (M=4096, N=6144, K=2048)
    gemm_tf32_kernel<<<dim3(3 * Cdim / 128, (Bsz * T) / 128), 256>>>(
        x, w_qkv, p_qkv, Cdim, Cdim, 3 * Cdim, 3 * Cdim);
    // 3. RMSNorm + RoPE + scatter into [BH,T,D]
    qkv_post_kernel<<<dim3(Bsz * T, H), 128>>>(qw, kw);
    // 4-6. fused flash attention -> g_y
    flash_attn_kernel<<<dim3(BH, T / 128), 256, FA_SMEM_BYTES>>>();
    // 7. out = y @ w_proj  (M=4096, N=2048, K=2048)
    gemm_tf32_kernel<<<dim3(Cdim / 128, (Bsz * T) / 128), 256>>>(
        p_y, w_proj, out, Cdim, Cdim, Cdim, Cdim);
}

// round 13
// speedup vs baseline: 1.5958x; 1.1806x over previous
#include <cuda_runtime.h>
#include <math.h>
#include <stdint.h>

#define Bsz 2
#define T 2048
#define Cdim 2048
#define H 16
#define D 128
#define BH (Bsz * H)
#define EPSV 1.1920929e-07f

// ---------------- scratch (static device allocations only) ----------------
__device__ __align__(128) float g_qkv[(size_t)Bsz * T * 3 * Cdim];   // 100 MB
__device__ __align__(128) float g_q[(size_t)BH * T * D];             // 32 MB
__device__ __align__(128) float g_k[(size_t)BH * T * D];             // 32 MB
__device__ __align__(128) float g_v[(size_t)BH * T * D];             // 32 MB
__device__ __align__(128) float g_y[(size_t)Bsz * T * Cdim];         // 32 MB
__device__ __align__(128) float g_cos[T * 64];
__device__ __align__(128) float g_sin[T * 64];

// ---------------- helpers ----------------
__device__ __forceinline__ uint32_t f2tf(float f) {
    uint32_t u;
    asm("cvt.rna.tf32.f32 %0, %1;" : "=r"(u) : "f"(f));
    return u;
}

__device__ __forceinline__ void mma_tf32(float* d, const uint32_t* a,
                                         uint32_t b0, uint32_t b1) {
    asm volatile(
        "mma.sync.aligned.m16n8k8.row.col.f32.tf32.tf32.f32 "
        "{%0,%1,%2,%3}, {%4,%5,%6,%7}, {%8,%9}, {%0,%1,%2,%3};\n"
        : "+f"(d[0]), "+f"(d[1]), "+f"(d[2]), "+f"(d[3])
        : "r"(a[0]), "r"(a[1]), "r"(a[2]), "r"(a[3]), "r"(b0), "r"(b1));
}

// ---------------- RoPE tables ----------------
__global__ void rope_tables_kernel() {
    int t = blockIdx.x;
    int j = threadIdx.x;  // 0..63
    double inv = exp(-((double)j / 64.0) * 13.815510557964274);  // ln(1e6)
    double a = (double)t * inv;
    g_cos[t * 64 + j] = (float)cos(a);
    g_sin[t * 64 + j] = (float)sin(a);
}

// ---------------- TF32 MMA tile core ----------------
// R3 core + octet-major non-BT B slab (injective, conflict-reduced):
//   addr(n, slot) = (n>>3)*84 + (n&7)*10 + slot,  slab = 16*84 = 1344 words.
// Store banks across lanes: 20*l mod 32 -> 8 distinct banks (was 2).
// Fragment reads keep the g*10 + c*2 intra-pattern (conflict-free, aligned).
// BT path and A path unchanged from the measured-good R3 version.
#define BSLAB 1344
template <bool BT>
__device__ __forceinline__ void mma_tile(
    const float* __restrict__ A, int lda,
    const float* __restrict__ B, int ldb,
    float* __restrict__ C, int ldc,
    int K, int row0, int col0)
{
    __shared__ uint32_t As[2 * 1280];
    __shared__ uint32_t Bs[2 * BSLAB];

    const int tid  = threadIdx.x;
    const int warp = tid >> 5;
    const int lane = tid & 31;
    const int g = lane >> 2;
    const int c = lane & 3;
    const int wm = (warp >> 1) * 32;
    const int wn = (warp & 1) * 64;

    const int a_row = tid >> 1;
    const int a_kc  = (tid & 1) << 3;
    const float* Ap = A + (size_t)(row0 + a_row) * lda + a_kc;
    uint32_t* As_st = As + (tid & 1) * 1280 + a_row * 10;

    const float* Bp;
    uint32_t* Bs_st;
    int b_coff = 0;
    if (BT) {
        const int n  = tid >> 1;
        const int kc = (tid & 1) << 3;
        Bp = B + (size_t)(col0 + n) * ldb + kc;
        Bs_st = Bs + (tid & 1) * BSLAB + n * 10;
    } else {
        const int kr = tid >> 4;
        const int nc = (tid & 15) << 3;
        Bp = B + (size_t)kr * ldb + col0 + nc;
        const int kk = kr & 7;
        b_coff = ((kk & 3) << 1) + (kk >> 2);
        // octet-major: octet = tid&15, stores at +t2*10 within the octet
        Bs_st = Bs + (kr >> 3) * BSLAB + (tid & 15) * 84 + b_coff;
    }

    float acc[2][8][4];
#pragma unroll
    for (int i = 0; i < 2; i++)
#pragma unroll
        for (int j = 0; j < 8; j++)
#pragma unroll
            for (int r = 0; r < 4; r++) acc[i][j][r] = 0.f;

    const int kperm[8] = {0, 2, 4, 6, 1, 3, 5, 7};

    for (int k0 = 0; k0 < K; k0 += 16) {
        float4 av0 = *(const float4*)(Ap + k0);
        float4 av1 = *(const float4*)(Ap + k0 + 4);
        float4 bv0, bv1;
        if (BT) {
            bv0 = *(const float4*)(Bp + k0);
            bv1 = *(const float4*)(Bp + k0 + 4);
        } else {
            bv0 = *(const float4*)(Bp + (size_t)k0 * ldb);
            bv1 = *(const float4*)(Bp + (size_t)k0 * ldb + 4);
        }
        __syncthreads();
        {
            float av[8] = {av0.x, av0.y, av0.z, av0.w, av1.x, av1.y, av1.z, av1.w};
#pragma unroll
            for (int t2 = 0; t2 < 8; t2++) As_st[kperm[t2]] = f2tf(av[t2]);
            float bvv[8] = {bv0.x, bv0.y, bv0.z, bv0.w, bv1.x, bv1.y, bv1.z, bv1.w};
            if (BT) {
#pragma unroll
                for (int t2 = 0; t2 < 8; t2++) Bs_st[kperm[t2]] = f2tf(bvv[t2]);
            } else {
#pragma unroll
                for (int t2 = 0; t2 < 8; t2++) Bs_st[t2 * 10] = f2tf(bvv[t2]);
            }
        }
        __syncthreads();

#pragma unroll
        for (int ks = 0; ks < 2; ks++) {
            const uint32_t* as = As + ks * 1280;
            const uint32_t* bs = Bs + ks * BSLAB;
            uint32_t a[2][4];
#pragma unroll
            for (int i = 0; i < 2; i++) {
                int r = wm + i * 16 + g;
                uint2 lo = *(const uint2*)&as[r * 10 + c * 2];
                uint2 hi = *(const uint2*)&as[(r + 8) * 10 + c * 2];
                a[i][0] = lo.x; a[i][1] = hi.x; a[i][2] = lo.y; a[i][3] = hi.y;
            }
#pragma unroll
            for (int j = 0; j < 8; j++) {
                uint2 bb;
                if (BT) {
                    int n = wn + j * 8 + g;
                    bb = *(const uint2*)&bs[n * 10 + c * 2];
                } else {
                    bb = *(const uint2*)&bs[((wn >> 3) + j) * 84 + g * 10 + c * 2];
                }
#pragma unroll
                for (int i = 0; i < 2; i++)
                    mma_tf32(acc[i][j], a[i], bb.x, bb.y);
            }
        }
    }

#pragma unroll
    for (int i = 0; i < 2; i++) {
        int r0 = row0 + wm + i * 16 + g;
#pragma unroll
        for (int j = 0; j < 8; j++) {
            int col = col0 + wn + j * 8 + c * 2;
            *(float2*)&C[(size_t)r0 * ldc + col] = make_float2(acc[i][j][0], acc[i][j][1]);
            *(float2*)&C[(size_t)(r0 + 8) * ldc + col] = make_float2(acc[i][j][2], acc[i][j][3]);
        }
    }
}

__global__ __launch_bounds__(256, 2)
void gemm_tf32_kernel(const float* __restrict__ A, const float* __restrict__ B,
                      float* __restrict__ C, int K, int lda, int ldb, int ldc)
{
    mma_tile<false>(A, lda, B, ldb, C, ldc, K, blockIdx.y * 128, blockIdx.x * 128);
}

// ---------------- fused flash attention ----------------
// One block = (bh, 128 q rows). S = QK^T (BT staging) -> online softmax in
// regs -> P to smem in A-fragment layout -> O += P V (octet-major V staging).
#define FA_SMEM_U32 (2560 + 2 * BSLAB + 20480 + 512)
#define FA_SMEM_BYTES (FA_SMEM_U32 * 4)

__global__ __launch_bounds__(256, 1)
void flash_attn_kernel()
{
    extern __shared__ uint32_t sm[];
    uint32_t* As = sm;
    uint32_t* Bs = sm + 2560;
    uint32_t* Ps = sm + 2560 + 2 * BSLAB;
    float* sm_m = (float*)(Ps + 20480);   // [2][128]
    float* sm_l = sm_m + 256;             // [2][128]

    const int bh = blockIdx.x;
    const int qt = (int)gridDim.y - 1 - (int)blockIdx.y;   // heavy tiles first
    const float* Q  = g_q + (size_t)bh * T * D;
    const float* Km = g_k + (size_t)bh * T * D;
    const float* V  = g_v + (size_t)bh * T * D;

    const int tid  = threadIdx.x;
    const int warp = tid >> 5;
    const int lane = tid & 31;
    const int g = lane >> 2;
    const int c = lane & 3;
    const int wm = (warp >> 1) * 32;
    const int wn = (warp & 1) * 64;
    const int half = warp & 1;

    // Q staging (A role)
    const int a_row = tid >> 1;
    const float* Qp = Q + (size_t)(qt * 128 + a_row) * D + ((tid & 1) << 3);
    uint32_t* As_st = As + (tid & 1) * 1280 + a_row * 10;
    // K staging (BT role)
    uint32_t* Bs_stK = Bs + (tid & 1) * BSLAB + (tid >> 1) * 10;
    // V staging (octet-major non-BT role)
    const int kr = tid >> 4;
    const int nc = (tid & 15) << 3;
    const int kk7 = kr & 7;
    const int v_coff = ((kk7 & 3) << 1) + (kk7 >> 2);
    uint32_t* Bs_stV = Bs + (kr >> 3) * BSLAB + (tid & 15) * 84 + v_coff;

    const int kperm[8] = {0, 2, 4, 6, 1, 3, 5, 7};
    const int slot0 = ((c & 1) << 2) | (c >> 1);   // P-store slot for k=2c

    float oacc[2][8][4];
#pragma unroll
    for (int i = 0; i < 2; i++)
#pragma unroll
        for (int j = 0; j < 8; j++)
#pragma unroll
            for (int r = 0; r < 4; r++) oacc[i][j][r] = 0.f;

    float mrow[4], lsum[4];
    int lr[4];
#pragma unroll
    for (int q = 0; q < 4; q++) {
        mrow[q] = -1e30f; lsum[q] = 0.f;
        lr[q] = wm + 16 * (q >> 1) + 8 * (q & 1) + g;
    }
    const float scale = 1.0f / (float)D;

    for (int kt = 0; kt <= qt; kt++) {
        // ======== S = Q @ K^T over this k-tile ========
        float acc[2][8][4];
#pragma unroll
        for (int i = 0; i < 2; i++)
#pragma unroll
            for (int j = 0; j < 8; j++)
#pragma unroll
                for (int r = 0; r < 4; r++) acc[i][j][r] = 0.f;

        const float* Kp = Km + (size_t)(kt * 128 + (tid >> 1)) * D + ((tid & 1) << 3);
        for (int k0 = 0; k0 < 128; k0 += 16) {
            float4 av0 = *(const float4*)(Qp + k0);
            float4 av1 = *(const float4*)(Qp + k0 + 4);
            float4 bv0 = *(const float4*)(Kp + k0);
            float4 bv1 = *(const float4*)(Kp + k0 + 4);
            __syncthreads();
            {
                float av[8] = {av0.x, av0.y, av0.z, av0.w, av1.x, av1.y, av1.z, av1.w};
                float bv[8] = {bv0.x, bv0.y, bv0.z, bv0.w, bv1.x, bv1.y, bv1.z, bv1.w};
#pragma unroll
                for (int t2 = 0; t2 < 8; t2++) As_st[kperm[t2]] = f2tf(av[t2]);
#pragma unroll
                for (int t2 = 0; t2 < 8; t2++) Bs_stK[kperm[t2]] = f2tf(bv[t2]);
            }
            __syncthreads();
#pragma unroll
            for (int ks = 0; ks < 2; ks++) {
                const uint32_t* as = As + ks * 1280;
                const uint32_t* bs = Bs + ks * BSLAB;
                uint32_t a[2][4];
#pragma unroll
                for (int i = 0; i < 2; i++) {
                    int r = wm + i * 16 + g;
                    uint2 lo = *(const uint2*)&as[r * 10 + c * 2];
                    uint2 hi = *(const uint2*)&as[(r + 8) * 10 + c * 2];
                    a[i][0] = lo.x; a[i][1] = hi.x; a[i][2] = lo.y; a[i][3] = hi.y;
                }
#pragma unroll
                for (int j = 0; j < 8; j++) {
                    int n = wn + j * 8 + g;
                    uint2 bb = *(const uint2*)&bs[n * 10 + c * 2];
#pragma unroll
                    for (int i = 0; i < 2; i++)
                        mma_tf32(acc[i][j], a[i], bb.x, bb.y);
                }
            }
        }

        // ======== online softmax update ========
        const bool diag = (kt == qt);
#pragma unroll
        for (int q = 0; q < 4; q++) {
            const int i = q >> 1, rb = (q & 1) * 2;
            float rm = -1e30f;
#pragma unroll
            for (int j = 0; j < 8; j++) {
#pragma unroll
                for (int v = 0; v < 2; v++) {
                    float s = acc[i][j][rb + v] * scale;
                    if (diag && (wn + 8 * j + 2 * c + v > lr[q])) s = -1e30f;
                    acc[i][j][rb + v] = s;
                    rm = fmaxf(rm, s);
                }
            }
            rm = fmaxf(rm, __shfl_xor_sync(0xffffffffu, rm, 1));
            rm = fmaxf(rm, __shfl_xor_sync(0xffffffffu, rm, 2));
            if (c == 0) sm_m[half * 128 + lr[q]] = rm;
        }
        __syncthreads();
        float alpha_s[4];
#pragma unroll
        for (int q = 0; q < 4; q++) {
            const int i = q >> 1, rb = (q & 1) * 2;
            float tm = fmaxf(sm_m[lr[q]], sm_m[128 + lr[q]]);
            float nm = fmaxf(mrow[q], tm);
            float alpha = expf(mrow[q] - nm);
            mrow[q] = nm;
            alpha_s[q] = alpha;
            float rs = 0.f;
#pragma unroll
            for (int j = 0; j < 8; j++) {
#pragma unroll
                for (int v = 0; v < 2; v++) {
                    float p = expf(acc[i][j][rb + v] - nm);
                    acc[i][j][rb + v] = p;
                    rs += p;
                }
            }
            rs += __shfl_xor_sync(0xffffffffu, rs, 1);
            rs += __shfl_xor_sync(0xffffffffu, rs, 2);
            if (c == 0) sm_l[half * 128 + lr[q]] = rs;
#pragma unroll
            for (int j = 0; j < 8; j++) {
                oacc[i][j][rb]     *= alpha;
                oacc[i][j][rb + 1] *= alpha;
            }
        }
        __syncthreads();
#pragma unroll
        for (int q = 0; q < 4; q++)
            lsum[q] = lsum[q] * alpha_s[q] + sm_l[lr[q]] + sm_l[128 + lr[q]];

        // ======== store P (tf32) into A-fragment layout ========
#pragma unroll
        for (int q = 0; q < 4; q++) {
            const int i = q >> 1, rb = (q & 1) * 2;
            uint32_t* prow = Ps + lr[q] * 10;
#pragma unroll
            for (int j = 0; j < 8; j++) {
                uint32_t* pp = prow + ((wn >> 3) + j) * 1280;
                pp[slot0]     = f2tf(acc[i][j][rb]);
                pp[slot0 + 2] = f2tf(acc[i][j][rb + 1]);
            }
        }

        // ======== O += P @ V ========
        for (int sl = 0; sl < 8; sl++) {
            const float* vp = V + (size_t)(kt * 128 + sl * 16 + kr) * D + nc;
            float4 w0 = *(const float4*)vp;
            float4 w1 = *(const float4*)(vp + 4);
            __syncthreads();   // also makes P stores visible before first read
            {
                float bvv[8] = {w0.x, w0.y, w0.z, w0.w, w1.x, w1.y, w1.z, w1.w};
#pragma unroll
                for (int t2 = 0; t2 < 8; t2++)
                    Bs_stV[t2 * 10] = f2tf(bvv[t2]);
            }
            __syncthreads();
#pragma unroll
            for (int ks = 0; ks < 2; ks++) {
                const uint32_t* as = Ps + (sl * 2 + ks) * 1280;
                const uint32_t* bs = Bs + ks * BSLAB;
                uint32_t a[2][4];
#pragma unroll
                for (int i = 0; i < 2; i++) {
                    int r = wm + i * 16 + g;
                    uint2 lo = *(const uint2*)&as[r * 10 + c * 2];
                    uint2 hi = *(const uint2*)&as[(r + 8) * 10 + c * 2];
                    a[i][0] = lo.x; a[i][1] = hi.x; a[i][2] = lo.y; a[i][3] = hi.y;
                }
#pragma unroll
                for (int j = 0; j < 8; j++) {
                    uint2 bb = *(const uint2*)&bs[((wn >> 3) + j) * 84 + g * 10 + c * 2];
#pragma unroll
                    for (int i = 0; i < 2; i++)
                        mma_tf32(oacc[i][j], a[i], bb.x, bb.y);
                }
            }
        }
    }

    // ======== epilogue: normalize and write to [B,T,C] ========
    const int b = bh >> 4;
    const int h = bh & 15;
    float* Cbase = g_y + (size_t)b * T * Cdim + h * D;
#pragma unroll
    for (int i = 0; i < 2; i++) {
#pragma unroll
        for (int rp = 0; rp < 2; rp++) {
            const int q = i * 2 + rp;
            const int row = qt * 128 + lr[q];
            const float inv = 1.0f / lsum[q];
            const int rb = rp * 2;
#pragma unroll
            for (int j = 0; j < 8; j++) {
                int col = wn + j * 8 + c * 2;
                *(float2*)&Cbase[(size_t)row * Cdim + col] =
                    make_float2(oacc[i][j][rb] * inv, oacc[i][j][rb + 1] * inv);
            }
        }
    }
}

// ---------------- RMSNorm + RoPE + scatter ----------------
__global__ __launch_bounds__(128)
void qkv_post_kernel(const float* __restrict__ qw, const float* __restrict__ kw)
{
    const int bt = blockIdx.x;
    const int h  = blockIdx.y;
    const int d  = threadIdx.x;
    const int t  = bt & (T - 1);
    const int b  = bt >> 11;
    const float* base = g_qkv + (size_t)bt * (3 * Cdim);
    float qv = base[h * D + d];
    float kv = base[Cdim + h * D + d];
    float vv = base[2 * Cdim + h * D + d];

    float q2 = qv * qv, k2 = kv * kv;
#pragma unroll
    for (int off = 16; off; off >>= 1) {
        q2 += __shfl_xor_sync(0xffffffffu, q2, off);
        k2 += __shfl_xor_sync(0xffffffffu, k2, off);
    }
    __shared__ float rq[4], rk[4];
    if ((d & 31) == 0) { rq[d >> 5] = q2; rk[d >> 5] = k2; }
    __syncthreads();
    float qms = (rq[0] + rq[1] + rq[2] + rq[3]) * (1.f / D);
    float kms = (rk[0] + rk[1] + rk[2] + rk[3]) * (1.f / D);
    float qn = qv * rsqrtf(qms + EPSV) * qw[d];
    float kn = kv * rsqrtf(kms + EPSV) * kw[d];

    __shared__ float sq[128], sk[128];
    sq[d] = qn; sk[d] = kn;
    __syncthreads();
    int j = d & 63;
    float cc = g_cos[t * 64 + j];
    float ss = g_sin[t * 64 + j];
    float qo, ko;
    if (d < 64) { qo = qn * cc - sq[d + 64] * ss; ko = kn * cc - sk[d + 64] * ss; }
    else        { qo = qn * cc + sq[d - 64] * ss; ko = kn * cc + sk[d - 64] * ss; }

    const size_t o = (((size_t)(b * H + h)) * T + t) * D + d;
    g_q[o] = qo; g_k[o] = ko; g_v[o] = vv;
}

// ---------------- launcher ----------------
extern "C" void kernel_launch(void* const* d_in, const int* in_sizes, int n_in,
                              void* d_out, int out_size)
{
    const float* x      = (const float*)d_in[0];
    const float* w_qkv  = (const float*)d_in[1];
    const float* w_proj = (const float*)d_in[2];
    const float* qw     = (const float*)d_in[3];
    const float* kw     = (const float*)d_in[4];
    float* out = (float*)d_out;

    float *p_qkv = nullptr, *p_y = nullptr;
    cudaGetSymbolAddress((void**)&p_qkv, g_qkv);
    cudaGetSymbolAddress((void**)&p_y, g_y);

    cudaFuncSetAttribute(flash_attn_kernel,
                         cudaFuncAttributeMaxDynamicSharedMemorySize,
                         FA_SMEM_BYTES);

    // 1. RoPE tables
    rope_tables_kernel<<<T, 64>>>();
    // 2. qkv = x @ w_qkv   (M=4096, N=6144, K=2048)
    gemm_tf32_kernel<<<dim3(3 * Cdim / 128, (Bsz * T) / 128), 256>>>(
        x, w_qkv, p_qkv, Cdim, Cdim, 3 * Cdim, 3 * Cdim);
    // 3. RMSNorm + RoPE + scatter into [BH,T,D]
    qkv_post_kernel<<<dim3(Bsz * T, H), 128>>>(qw, kw);
    // 4-6. fused flash attention -> g_y
    flash_attn_kernel<<<dim3(BH, T / 128), 256, FA_SMEM_BYTES>>>();
    // 7. out = y @ w_proj  (M=4096, N=2048, K=2048)
    gemm_tf32_kernel<<<dim3(Cdim / 128, (Bsz * T) / 128), 256>>>(
        p_y, w_proj, out, Cdim, Cdim, Cdim, Cdim);
}

// round 15
// speedup vs baseline: 1.7354x; 1.0875x over previous
#include <cuda_runtime.h>
#include <math.h>
#include <stdint.h>

#define Bsz 2
#define T 2048
#define Cdim 2048
#define H 16
#define D 128
#define BH (Bsz * H)
#define EPSV 1.1920929e-07f

// ---------------- scratch (static device allocations only) ----------------
__device__ __align__(128) float g_qkv[(size_t)Bsz * T * 3 * Cdim];   // 100 MB
__device__ __align__(128) float g_q[(size_t)BH * T * D];             // 32 MB
__device__ __align__(128) float g_k[(size_t)BH * T * D];             // 32 MB
__device__ __align__(128) float g_v[(size_t)BH * T * D];             // 32 MB
__device__ __align__(128) float g_y[(size_t)Bsz * T * Cdim];         // 32 MB
__device__ __align__(128) float g_cos[T * 64];
__device__ __align__(128) float g_sin[T * 64];

// ---------------- helpers ----------------
__device__ __forceinline__ uint32_t f2tf(float f) {
    uint32_t u;
    asm("cvt.rna.tf32.f32 %0, %1;" : "=r"(u) : "f"(f));
    return u;
}

__device__ __forceinline__ void mma_tf32(float* d, const uint32_t* a,
                                         uint32_t b0, uint32_t b1) {
    asm volatile(
        "mma.sync.aligned.m16n8k8.row.col.f32.tf32.tf32.f32 "
        "{%0,%1,%2,%3}, {%4,%5,%6,%7}, {%8,%9}, {%0,%1,%2,%3};\n"
        : "+f"(d[0]), "+f"(d[1]), "+f"(d[2]), "+f"(d[3])
        : "r"(a[0]), "r"(a[1]), "r"(a[2]), "r"(a[3]), "r"(b0), "r"(b1));
}

// ---------------- RoPE tables ----------------
__global__ void rope_tables_kernel() {
    int t = blockIdx.x;
    int j = threadIdx.x;  // 0..63
    double inv = exp(-((double)j / 64.0) * 13.815510557964274);  // ln(1e6)
    double a = (double)t * inv;
    g_cos[t * 64 + j] = (float)cos(a);
    g_sin[t * 64 + j] = (float)sin(a);
}

// ---------------- TF32 MMA tile core (unchanged from measured R13) ----------------
#define BSLAB 1344
template <bool BT>
__device__ __forceinline__ void mma_tile(
    const float* __restrict__ A, int lda,
    const float* __restrict__ B, int ldb,
    float* __restrict__ C, int ldc,
    int K, int row0, int col0)
{
    __shared__ uint32_t As[2 * 1280];
    __shared__ uint32_t Bs[2 * BSLAB];

    const int tid  = threadIdx.x;
    const int warp = tid >> 5;
    const int lane = tid & 31;
    const int g = lane >> 2;
    const int c = lane & 3;
    const int wm = (warp >> 1) * 32;
    const int wn = (warp & 1) * 64;

    const int a_row = tid >> 1;
    const int a_kc  = (tid & 1) << 3;
    const float* Ap = A + (size_t)(row0 + a_row) * lda + a_kc;
    uint32_t* As_st = As + (tid & 1) * 1280 + a_row * 10;

    const float* Bp;
    uint32_t* Bs_st;
    int b_coff = 0;
    if (BT) {
        const int n  = tid >> 1;
        const int kc = (tid & 1) << 3;
        Bp = B + (size_t)(col0 + n) * ldb + kc;
        Bs_st = Bs + (tid & 1) * BSLAB + n * 10;
    } else {
        const int kr = tid >> 4;
        const int nc = (tid & 15) << 3;
        Bp = B + (size_t)kr * ldb + col0 + nc;
        const int kk = kr & 7;
        b_coff = ((kk & 3) << 1) + (kk >> 2);
        Bs_st = Bs + (kr >> 3) * BSLAB + (tid & 15) * 84 + b_coff;
    }

    float acc[2][8][4];
#pragma unroll
    for (int i = 0; i < 2; i++)
#pragma unroll
        for (int j = 0; j < 8; j++)
#pragma unroll
            for (int r = 0; r < 4; r++) acc[i][j][r] = 0.f;

    const int kperm[8] = {0, 2, 4, 6, 1, 3, 5, 7};

    for (int k0 = 0; k0 < K; k0 += 16) {
        float4 av0 = *(const float4*)(Ap + k0);
        float4 av1 = *(const float4*)(Ap + k0 + 4);
        float4 bv0, bv1;
        if (BT) {
            bv0 = *(const float4*)(Bp + k0);
            bv1 = *(const float4*)(Bp + k0 + 4);
        } else {
            bv0 = *(const float4*)(Bp + (size_t)k0 * ldb);
            bv1 = *(const float4*)(Bp + (size_t)k0 * ldb + 4);
        }
        __syncthreads();
        {
            float av[8] = {av0.x, av0.y, av0.z, av0.w, av1.x, av1.y, av1.z, av1.w};
#pragma unroll
            for (int t2 = 0; t2 < 8; t2++) As_st[kperm[t2]] = f2tf(av[t2]);
            float bvv[8] = {bv0.x, bv0.y, bv0.z, bv0.w, bv1.x, bv1.y, bv1.z, bv1.w};
            if (BT) {
#pragma unroll
                for (int t2 = 0; t2 < 8; t2++) Bs_st[kperm[t2]] = f2tf(bvv[t2]);
            } else {
#pragma unroll
                for (int t2 = 0; t2 < 8; t2++) Bs_st[t2 * 10] = f2tf(bvv[t2]);
            }
        }
        __syncthreads();

#pragma unroll
        for (int ks = 0; ks < 2; ks++) {
            const uint32_t* as = As + ks * 1280;
            const uint32_t* bs = Bs + ks * BSLAB;
            uint32_t a[2][4];
#pragma unroll
            for (int i = 0; i < 2; i++) {
                int r = wm + i * 16 + g;
                uint2 lo = *(const uint2*)&as[r * 10 + c * 2];
                uint2 hi = *(const uint2*)&as[(r + 8) * 10 + c * 2];
                a[i][0] = lo.x; a[i][1] = hi.x; a[i][2] = lo.y; a[i][3] = hi.y;
            }
#pragma unroll
            for (int j = 0; j < 8; j++) {
                uint2 bb;
                if (BT) {
                    int n = wn + j * 8 + g;
                    bb = *(const uint2*)&bs[n * 10 + c * 2];
                } else {
                    bb = *(const uint2*)&bs[((wn >> 3) + j) * 84 + g * 10 + c * 2];
                }
#pragma unroll
                for (int i = 0; i < 2; i++)
                    mma_tf32(acc[i][j], a[i], bb.x, bb.y);
            }
        }
    }

#pragma unroll
    for (int i = 0; i < 2; i++) {
        int r0 = row0 + wm + i * 16 + g;
#pragma unroll
        for (int j = 0; j < 8; j++) {
            int col = col0 + wn + j * 8 + c * 2;
            *(float2*)&C[(size_t)r0 * ldc + col] = make_float2(acc[i][j][0], acc[i][j][1]);
            *(float2*)&C[(size_t)(r0 + 8) * ldc + col] = make_float2(acc[i][j][2], acc[i][j][3]);
        }
    }
}

__global__ __launch_bounds__(256, 2)
void gemm_tf32_kernel(const float* __restrict__ A, const float* __restrict__ B,
                      float* __restrict__ C, int K, int lda, int ldb, int ldc)
{
    mma_tile<false>(A, lda, B, ldb, C, ldc, K, blockIdx.y * 128, blockIdx.x * 128);
}

// ---------------- fused flash attention (half-tile staging, 10 syncs/tile) ----
// Smem (u32): QS 16*1280 = 20480  (persistent Q, A-fragment layout, ALL 16 slabs)
//             KVS 8*1344 = 10752  (64-deep half of K (BT) or V (octet-major))
//             Ps 16*1280 = 20480  (P in A-fragment layout)
//             stats 512
// Total 52224 u32 = 208896 B (fits 227 KB limit).
#define FA_SMEM_U32 (20480 + 10752 + 20480 + 512)
#define FA_SMEM_BYTES (FA_SMEM_U32 * 4)

__global__ __launch_bounds__(256, 1)
void flash_attn_kernel()
{
    extern __shared__ uint32_t sm[];
    uint32_t* QS  = sm;              // 20480
    uint32_t* KVS = sm + 20480;      // 10752
    uint32_t* Ps  = sm + 31232;      // 20480
    float* sm_m = (float*)(sm + 51712);   // [2][128]
    float* sm_l = sm_m + 256;             // [2][128]

    const int bh = blockIdx.x;
    const int qt = (int)gridDim.y - 1 - (int)blockIdx.y;   // heavy tiles first
    const float* Q  = g_q + (size_t)bh * T * D;
    const float* Km = g_k + (size_t)bh * T * D;
    const float* V  = g_v + (size_t)bh * T * D;

    const int tid  = threadIdx.x;
    const int warp = tid >> 5;
    const int lane = tid & 31;
    const int g = lane >> 2;
    const int c = lane & 3;
    const int wm = (warp >> 1) * 32;
    const int wn = (warp & 1) * 64;
    const int half = warp & 1;

    const int kperm[8] = {0, 2, 4, 6, 1, 3, 5, 7};
    const int slot0 = ((c & 1) << 2) | (c >> 1);   // P-store slot for k=2c

    // staging maps
    const int a_row = tid >> 1;                     // Q/K row covered
    const int kr = tid >> 4;                        // V row-within-16
    const int nc = (tid & 15) << 3;                 // V d-offset
    const int kk7 = kr & 7;
    const int v_coff = ((kk7 & 3) << 1) + (kk7 >> 2);
    uint32_t* QS_st = QS  + (tid & 1) * 1280 + a_row * 10;
    uint32_t* KS_st = KVS + (tid & 1) * 1344 + a_row * 10;
    uint32_t* VS_st = KVS + (kr >> 3) * 1344 + (tid & 15) * 84 + v_coff;

    // ---- stage Q once (persistent, all 16 slabs) ----
    {
        const float* Qp = Q + (size_t)(qt * 128 + a_row) * D + ((tid & 1) << 3);
#pragma unroll
        for (int k0 = 0; k0 < 128; k0 += 16) {
            float4 v0 = *(const float4*)(Qp + k0);
            float4 v1 = *(const float4*)(Qp + k0 + 4);
            float av[8] = {v0.x, v0.y, v0.z, v0.w, v1.x, v1.y, v1.z, v1.w};
            uint32_t* st = QS_st + (k0 >> 3) * 1280;
#pragma unroll
            for (int t2 = 0; t2 < 8; t2++) st[kperm[t2]] = f2tf(av[t2]);
        }
    }
    // QS visibility is covered by the first K-staging barrier below.

    float oacc[2][8][4];
#pragma unroll
    for (int i = 0; i < 2; i++)
#pragma unroll
        for (int j = 0; j < 8; j++)
#pragma unroll
            for (int r = 0; r < 4; r++) oacc[i][j][r] = 0.f;

    float mrow[4], lsum[4];
    int lr[4];
#pragma unroll
    for (int q = 0; q < 4; q++) {
        mrow[q] = -1e30f; lsum[q] = 0.f;
        lr[q] = wm + 16 * (q >> 1) + 8 * (q & 1) + g;
    }
    const float scale = 1.0f / (float)D;

    for (int kt = 0; kt <= qt; kt++) {
        float acc[2][8][4];
#pragma unroll
        for (int i = 0; i < 2; i++)
#pragma unroll
            for (int j = 0; j < 8; j++)
#pragma unroll
                for (int r = 0; r < 4; r++) acc[i][j][r] = 0.f;

        // ---- S = Q @ K^T in two 64-deep halves ----
#pragma unroll
        for (int h2 = 0; h2 < 2; h2++) {
            __syncthreads();   // KVS free (prev PV / prev half reads done)
            {
                const float* Kp = Km + (size_t)(kt * 128 + a_row) * D
                                + h2 * 64 + ((tid & 1) << 3);
#pragma unroll
                for (int k0 = 0; k0 < 64; k0 += 16) {
                    float4 v0 = *(const float4*)(Kp + k0);
                    float4 v1 = *(const float4*)(Kp + k0 + 4);
                    float bv[8] = {v0.x, v0.y, v0.z, v0.w, v1.x, v1.y, v1.z, v1.w};
                    uint32_t* st = KS_st + (k0 >> 3) * 1344;
#pragma unroll
                    for (int t2 = 0; t2 < 8; t2++) st[kperm[t2]] = f2tf(bv[t2]);
                }
            }
            __syncthreads();
#pragma unroll
            for (int ks = 0; ks < 8; ks++) {
                const uint32_t* as = QS + (h2 * 8 + ks) * 1280;
                const uint32_t* bs = KVS + ks * 1344;
                uint32_t a[2][4];
#pragma unroll
                for (int i = 0; i < 2; i++) {
                    int r = wm + i * 16 + g;
                    uint2 lo = *(const uint2*)&as[r * 10 + c * 2];
                    uint2 hi = *(const uint2*)&as[(r + 8) * 10 + c * 2];
                    a[i][0] = lo.x; a[i][1] = hi.x; a[i][2] = lo.y; a[i][3] = hi.y;
                }
#pragma unroll
                for (int j = 0; j < 8; j++) {
                    int n = wn + j * 8 + g;
                    uint2 bb = *(const uint2*)&bs[n * 10 + c * 2];
#pragma unroll
                    for (int i = 0; i < 2; i++)
                        mma_tf32(acc[i][j], a[i], bb.x, bb.y);
                }
            }
        }

        // ---- online softmax update ----
        const bool diag = (kt == qt);
#pragma unroll
        for (int q = 0; q < 4; q++) {
            const int i = q >> 1, rb = (q & 1) * 2;
            float rm = -1e30f;
#pragma unroll
            for (int j = 0; j < 8; j++) {
#pragma unroll
                for (int v = 0; v < 2; v++) {
                    float s = acc[i][j][rb + v] * scale;
                    if (diag && (wn + 8 * j + 2 * c + v > lr[q])) s = -1e30f;
                    acc[i][j][rb + v] = s;
                    rm = fmaxf(rm, s);
                }
            }
            rm = fmaxf(rm, __shfl_xor_sync(0xffffffffu, rm, 1));
            rm = fmaxf(rm, __shfl_xor_sync(0xffffffffu, rm, 2));
            if (c == 0) sm_m[half * 128 + lr[q]] = rm;
        }
        __syncthreads();
        float alpha_s[4];
#pragma unroll
        for (int q = 0; q < 4; q++) {
            const int i = q >> 1, rb = (q & 1) * 2;
            float tm = fmaxf(sm_m[lr[q]], sm_m[128 + lr[q]]);
            float nm = fmaxf(mrow[q], tm);
            float alpha = expf(mrow[q] - nm);
            mrow[q] = nm;
            alpha_s[q] = alpha;
            float rs = 0.f;
#pragma unroll
            for (int j = 0; j < 8; j++) {
#pragma unroll
                for (int v = 0; v < 2; v++) {
                    float p = expf(acc[i][j][rb + v] - nm);
                    acc[i][j][rb + v] = p;
                    rs += p;
                }
            }
            rs += __shfl_xor_sync(0xffffffffu, rs, 1);
            rs += __shfl_xor_sync(0xffffffffu, rs, 2);
            if (c == 0) sm_l[half * 128 + lr[q]] = rs;
#pragma unroll
            for (int j = 0; j < 8; j++) {
                oacc[i][j][rb]     *= alpha;
                oacc[i][j][rb + 1] *= alpha;
            }
        }
        __syncthreads();
#pragma unroll
        for (int q = 0; q < 4; q++)
            lsum[q] = lsum[q] * alpha_s[q] + sm_l[lr[q]] + sm_l[128 + lr[q]];

        // ---- store P (all 16 slabs, A-fragment layout) ----
#pragma unroll
        for (int q = 0; q < 4; q++) {
            const int i = q >> 1, rb = (q & 1) * 2;
            uint32_t* prow = Ps + lr[q] * 10;
#pragma unroll
            for (int j = 0; j < 8; j++) {
                uint32_t* pp = prow + ((wn >> 3) + j) * 1280;
                pp[slot0]     = f2tf(acc[i][j][rb]);
                pp[slot0 + 2] = f2tf(acc[i][j][rb + 1]);
            }
        }

        // ---- O += P @ V in two 64-key halves ----
#pragma unroll
        for (int h2 = 0; h2 < 2; h2++) {
            __syncthreads();   // KVS free; (h2==0) also publishes P stores
            {
                const float* Vb = V + (size_t)(kt * 128 + h2 * 64 + kr) * D + nc;
#pragma unroll
                for (int sl = 0; sl < 4; sl++) {
                    const float* vp = Vb + (size_t)(sl * 16) * D;
                    float4 w0 = *(const float4*)vp;
                    float4 w1 = *(const float4*)(vp + 4);
                    float bv[8] = {w0.x, w0.y, w0.z, w0.w, w1.x, w1.y, w1.z, w1.w};
                    uint32_t* st = VS_st + sl * 2 * 1344;
#pragma unroll
                    for (int t2 = 0; t2 < 8; t2++) st[t2 * 10] = f2tf(bv[t2]);
                }
            }
            __syncthreads();
#pragma unroll
            for (int ks = 0; ks < 8; ks++) {
                const uint32_t* as = Ps + (h2 * 8 + ks) * 1280;
                const uint32_t* bs = KVS + ks * 1344;
                uint32_t a[2][4];
#pragma unroll
                for (int i = 0; i < 2; i++) {
                    int r = wm + i * 16 + g;
                    uint2 lo = *(const uint2*)&as[r * 10 + c * 2];
                    uint2 hi = *(const uint2*)&as[(r + 8) * 10 + c * 2];
                    a[i][0] = lo.x; a[i][1] = hi.x; a[i][2] = lo.y; a[i][3] = hi.y;
                }
#pragma unroll
                for (int j = 0; j < 8; j++) {
                    uint2 bb = *(const uint2*)&bs[((wn >> 3) + j) * 84 + g * 10 + c * 2];
#pragma unroll
                    for (int i = 0; i < 2; i++)
                        mma_tf32(oacc[i][j], a[i], bb.x, bb.y);
                }
            }
        }
    }

    // ---- epilogue: normalize and write to [B,T,C] ----
    const int b = bh >> 4;
    const int h = bh & 15;
    float* Cbase = g_y + (size_t)b * T * Cdim + h * D;
#pragma unroll
    for (int i = 0; i < 2; i++) {
#pragma unroll
        for (int rp = 0; rp < 2; rp++) {
            const int q = i * 2 + rp;
            const int row = qt * 128 + lr[q];
            const float inv = 1.0f / lsum[q];
            const int rb = rp * 2;
#pragma unroll
            for (int j = 0; j < 8; j++) {
                int col = wn + j * 8 + c * 2;
                *(float2*)&Cbase[(size_t)row * Cdim + col] =
                    make_float2(oacc[i][j][rb] * inv, oacc[i][j][rb + 1] * inv);
            }
        }
    }
}

// ---------------- RMSNorm + RoPE + scatter ----------------
__global__ __launch_bounds__(128)
void qkv_post_kernel(const float* __restrict__ qw, const float* __restrict__ kw)
{
    const int bt = blockIdx.x;
    const int h  = blockIdx.y;
    const int d  = threadIdx.x;
    const int t  = bt & (T - 1);
    const int b  = bt >> 11;
    const float* base = g_qkv + (size_t)bt * (3 * Cdim);
    float qv = base[h * D + d];
    float kv = base[Cdim + h * D + d];
    float vv = base[2 * Cdim + h * D + d];

    float q2 = qv * qv, k2 = kv * kv;
#pragma unroll
    for (int off = 16; off; off >>= 1) {
        q2 += __shfl_xor_sync(0xffffffffu, q2, off);
        k2 += __shfl_xor_sync(0xffffffffu, k2, off);
    }
    __shared__ float rq[4], rk[4];
    if ((d & 31) == 0) { rq[d >> 5] = q2; rk[d >> 5] = k2; }
    __syncthreads();
    float qms = (rq[0] + rq[1] + rq[2] + rq[3]) * (1.f / D);
    float kms = (rk[0] + rk[1] + rk[2] + rk[3]) * (1.f / D);
    float qn = qv * rsqrtf(qms + EPSV) * qw[d];
    float kn = kv * rsqrtf(kms + EPSV) * kw[d];

    __shared__ float sq[128], sk[128];
    sq[d] = qn; sk[d] = kn;
    __syncthreads();
    int j = d & 63;
    float cc = g_cos[t * 64 + j];
    float ss = g_sin[t * 64 + j];
    float qo, ko;
    if (d < 64) { qo = qn * cc - sq[d + 64] * ss; ko = kn * cc - sk[d + 64] * ss; }
    else        { qo = qn * cc + sq[d - 64] * ss; ko = kn * cc + sk[d - 64] * ss; }

    const size_t o = (((size_t)(b * H + h)) * T + t) * D + d;
    g_q[o] = qo; g_k[o] = ko; g_v[o] = vv;
}

// ---------------- launcher ----------------
extern "C" void kernel_launch(void* const* d_in, const int* in_sizes, int n_in,
                              void* d_out, int out_size)
{
    const float* x      = (const float*)d_in[0];
    const float* w_qkv  = (const float*)d_in[1];
    const float* w_proj = (const float*)d_in[2];
    const float* qw     = (const float*)d_in[3];
    const float* kw     = (const float*)d_in[4];
    float* out = (float*)d_out;

    float *p_qkv = nullptr, *p_y = nullptr;
    cudaGetSymbolAddress((void**)&p_qkv, g_qkv);
    cudaGetSymbolAddress((void**)&p_y, g_y);

    cudaFuncSetAttribute(flash_attn_kernel,
                         cudaFuncAttributeMaxDynamicSharedMemorySize,
                         FA_SMEM_BYTES);

    // 1. RoPE tables
    rope_tables_kernel<<<T, 64>>>();
    // 2. qkv = x @ w_qkv   (M=4096, N=6144, K=2048)
    gemm_tf32_kernel<<<dim3(3 * Cdim / 128, (Bsz * T) / 128), 256>>>(
        x, w_qkv, p_qkv, Cdim, Cdim, 3 * Cdim, 3 * Cdim);
    // 3. RMSNorm + RoPE + scatter into [BH,T,D]
    qkv_post_kernel<<<dim3(Bsz * T, H), 128>>>(qw, kw);
    // 4-6. fused flash attention -> g_y
    flash_attn_kernel<<<dim3(BH, T / 128), 256, FA_SMEM_BYTES>>>();
    // 7. out = y @ w_proj  (M=4096, N=2048, K=2048)
    gemm_tf32_kernel<<<dim3(Cdim / 128, (Bsz * T) / 128), 256>>>(
        p_y, w_proj, out, Cdim, Cdim, Cdim, Cdim);
}